// round 8
// baseline (speedup 1.0000x reference)
#include <cuda_runtime.h>
#include <cstdint>

// LSTMDecoder: B=1024, A=H=16, R=128, T=128.
// 16 threads per batch element; lane j owns h_j, c_j, gate rows of W_hh.
// R7: h broadcast via shared memory (1 STS + syncwarp + 4 LDS.128) instead of
// 16 SHFLs (MIO serialization suspected binder). Gate-major fma.rn.f32x2 dot:
// h-pairs come straight from LDS.128 register quads (no duplication packs).
// Sigmoid 0.5-scale folded into i/f/o weights+biases.

#define NT 128

__device__ __forceinline__ float tanhapx(float x) {
    float r;
    asm("tanh.approx.f32 %0, %1;" : "=f"(r) : "f"(x));
    return r;
}
__device__ __forceinline__ uint64_t pack2(float lo, float hi) {
    uint64_t r;
    asm("mov.b64 %0, {%1, %2};" : "=l"(r) : "f"(lo), "f"(hi));
    return r;
}
__device__ __forceinline__ void unpack2(float& lo, float& hi, uint64_t v) {
    asm("mov.b64 {%0, %1}, %2;" : "=f"(lo), "=f"(hi) : "l"(v));
}
__device__ __forceinline__ uint64_t fma2v(uint64_t a, uint64_t b, uint64_t c) {
    uint64_t d;
    asm("fma.rn.f32x2 %0, %1, %2, %3;" : "=l"(d) : "l"(a), "l"(b), "l"(c));
    return d;
}
__device__ __forceinline__ uint64_t add2(uint64_t a, uint64_t b) {
    uint64_t r;
    asm("add.rn.f32x2 %0, %1, %2;" : "=l"(r) : "l"(a), "l"(b));
    return r;
}

__global__ __launch_bounds__(128, 1)
void lstm_decoder_kernel(
    const float* __restrict__ y,     // (B,16)
    const float* __restrict__ u,     // (B,128)
    const float* __restrict__ W_ih,  // (64,1)
    const float* __restrict__ W_hh,  // (64,16)
    const float* __restrict__ b_ih,  // (64)
    const float* __restrict__ b_hh,  // (64)
    const float* __restrict__ W_lin, // (1,16)
    const float* __restrict__ b_lin, // (1)
    const float* __restrict__ W_h0,  // (16,128)
    const float* __restrict__ b_h0,  // (16)
    const float* __restrict__ W_c0,  // (16,128)
    const float* __restrict__ b_c0,  // (16)
    float* __restrict__ out)         // (B,144)
{
    const int tid = blockIdx.x * blockDim.x + threadIdx.x;
    const int b   = tid >> 4;     // batch element
    const int j   = tid & 15;     // hidden index
    const unsigned FULL = 0xffffffffu;

    // shared h buffer: 8 batch elems per block x 16 floats
    __shared__ float sh[8 * 16];
    const int bb = threadIdx.x >> 4;          // batch slot in block
    float* shp = sh + bb * 16;                // this batch's h vector
    const float4* sh4 = (const float4*)shp;

    // ---- per-thread gate-major packed weight pairs over k ----
    // i,f,o rows pre-scaled by 0.5 (sigmoid folding); g unscaled.
    uint64_t Wi[8], Wf[8], Wg[8], Wo[8];
#pragma unroll
    for (int p = 0; p < 8; p++) {
        Wi[p] = pack2(0.5f * W_hh[(     j) * 16 + 2*p], 0.5f * W_hh[(     j) * 16 + 2*p+1]);
        Wf[p] = pack2(0.5f * W_hh[(16 + j) * 16 + 2*p], 0.5f * W_hh[(16 + j) * 16 + 2*p+1]);
        Wg[p] = pack2(       W_hh[(32 + j) * 16 + 2*p],        W_hh[(32 + j) * 16 + 2*p+1]);
        Wo[p] = pack2(0.5f * W_hh[(48 + j) * 16 + 2*p], 0.5f * W_hh[(48 + j) * 16 + 2*p+1]);
    }
    // x-term: acc_G init = fma2((x,x), (w_G, 0), (b_G, 0))
    const uint64_t wxi = pack2(0.5f * W_ih[j],      0.0f);
    const uint64_t wxf = pack2(0.5f * W_ih[16 + j], 0.0f);
    const uint64_t wxg = pack2(       W_ih[32 + j], 0.0f);
    const uint64_t wxo = pack2(0.5f * W_ih[48 + j], 0.0f);
    const uint64_t bvi = pack2(0.5f * (b_ih[j]      + b_hh[j]),      0.0f);
    const uint64_t bvf = pack2(0.5f * (b_ih[16 + j] + b_hh[16 + j]), 0.0f);
    const uint64_t bvg = pack2(       (b_ih[32 + j] + b_hh[32 + j]), 0.0f);
    const uint64_t bvo = pack2(0.5f * (b_ih[48 + j] + b_hh[48 + j]), 0.0f);
    const float wl = W_lin[j];
    const float bl = b_lin[0];

    // ---- h0 = u @ W_h0.T + b_h0 ; c0 = u @ W_c0.T + b_c0 ----
    float h = b_h0[j];
    float c = b_c0[j];
    {
        const float4* u4  = (const float4*)(u    + b * 128);
        const float4* wh4 = (const float4*)(W_h0 + j * 128);
        const float4* wc4 = (const float4*)(W_c0 + j * 128);
#pragma unroll 4
        for (int r = 0; r < 32; r++) {
            float4 uu = u4[r], wh = wh4[r], wc = wc4[r];
            h = fmaf(uu.x, wh.x, h); h = fmaf(uu.y, wh.y, h);
            h = fmaf(uu.z, wh.z, h); h = fmaf(uu.w, wh.w, h);
            c = fmaf(uu.x, wc.x, c); c = fmaf(uu.y, wc.y, c);
            c = fmaf(uu.z, wc.z, c); c = fmaf(uu.w, wc.w, c);
        }
    }

    // ---- window replicated per-thread: xs[s] = window[:, s] ----
    float xs[16];
    {
        const float4* y4 = (const float4*)(y + b * 16);
        float4 y0 = y4[0], y1 = y4[1], y2 = y4[2], y3 = y4[3];
        xs[0]=y0.x; xs[1]=y0.y; xs[2]=y0.z; xs[3]=y0.w;
        xs[4]=y1.x; xs[5]=y1.y; xs[6]=y1.z; xs[7]=y1.w;
        xs[8]=y2.x; xs[9]=y2.y; xs[10]=y2.z; xs[11]=y2.w;
        xs[12]=y3.x; xs[13]=y3.y; xs[14]=y3.z; xs[15]=y3.w;
    }
    out[b * 144 + j] = y[b * 16 + j];        // first 16 output cols = y
    float* outp = out + b * 144 + 16;

    for (int t = 0; t < NT; t++) {
#pragma unroll
        for (int s = 0; s < 16; s++) {
            // broadcast h through shared memory
            shp[j] = h;
            __syncwarp(FULL);
            float4 h03 = sh4[0], h47 = sh4[1], h8b = sh4[2], hcf = sh4[3];
            __syncwarp(FULL);   // LDS done before next cell's STS overwrites

            // h pairs straight from vector-load register quads
            uint64_t hp0 = pack2(h03.x, h03.y), hp1 = pack2(h03.z, h03.w);
            uint64_t hp2 = pack2(h47.x, h47.y), hp3 = pack2(h47.z, h47.w);
            uint64_t hp4 = pack2(h8b.x, h8b.y), hp5 = pack2(h8b.z, h8b.w);
            uint64_t hp6 = pack2(hcf.x, hcf.y), hp7 = pack2(hcf.z, hcf.w);

            uint64_t xd = pack2(xs[s], xs[s]);
            // even/odd split chains per gate (depth 5 / 4)
            uint64_t ai0 = fma2v(xd, wxi, bvi), ai1;
            uint64_t af0 = fma2v(xd, wxf, bvf), af1;
            uint64_t ag0 = fma2v(xd, wxg, bvg), ag1;
            uint64_t ao0 = fma2v(xd, wxo, bvo), ao1;
            ai0 = fma2v(hp0, Wi[0], ai0);  ai1 = fma2v(hp1, Wi[1], 0ull);
            af0 = fma2v(hp0, Wf[0], af0);  af1 = fma2v(hp1, Wf[1], 0ull);
            ag0 = fma2v(hp0, Wg[0], ag0);  ag1 = fma2v(hp1, Wg[1], 0ull);
            ao0 = fma2v(hp0, Wo[0], ao0);  ao1 = fma2v(hp1, Wo[1], 0ull);
            ai0 = fma2v(hp2, Wi[2], ai0);  ai1 = fma2v(hp3, Wi[3], ai1);
            af0 = fma2v(hp2, Wf[2], af0);  af1 = fma2v(hp3, Wf[3], af1);
            ag0 = fma2v(hp2, Wg[2], ag0);  ag1 = fma2v(hp3, Wg[3], ag1);
            ao0 = fma2v(hp2, Wo[2], ao0);  ao1 = fma2v(hp3, Wo[3], ao1);
            ai0 = fma2v(hp4, Wi[4], ai0);  ai1 = fma2v(hp5, Wi[5], ai1);
            af0 = fma2v(hp4, Wf[4], af0);  af1 = fma2v(hp5, Wf[5], af1);
            ag0 = fma2v(hp4, Wg[4], ag0);  ag1 = fma2v(hp5, Wg[5], ag1);
            ao0 = fma2v(hp4, Wo[4], ao0);  ao1 = fma2v(hp5, Wo[5], ao1);
            ai0 = fma2v(hp6, Wi[6], ai0);  ai1 = fma2v(hp7, Wi[7], ai1);
            af0 = fma2v(hp6, Wf[6], af0);  af1 = fma2v(hp7, Wf[7], af1);
            ag0 = fma2v(hp6, Wg[6], ag0);  ag1 = fma2v(hp7, Wg[7], ag1);
            ao0 = fma2v(hp6, Wo[6], ao0);  ao1 = fma2v(hp7, Wo[7], ao1);

            float lo, hi;
            unpack2(lo, hi, add2(ai0, ai1)); float ai = lo + hi;
            unpack2(lo, hi, add2(af0, af1)); float af = lo + hi;
            unpack2(lo, hi, add2(ag0, ag1)); float ag = lo + hi;
            unpack2(lo, hi, add2(ao0, ao1)); float ao = lo + hi;

            // i/f/o pre-acts already carry the 0.5 scale
            float ig = fmaf(0.5f, tanhapx(ai), 0.5f);
            float fg = fmaf(0.5f, tanhapx(af), 0.5f);
            float gg = tanhapx(ag);
            float og = fmaf(0.5f, tanhapx(ao), 0.5f);
            c = fmaf(fg, c, ig * gg);
            h = og * tanhapx(c);
        }
        // pred = sum_j h_j * W_lin_j + b_lin (feeds xs[15], consumed 15 cells
        // later -> off the critical path)
        float p = h * wl;
#pragma unroll
        for (int off = 8; off; off >>= 1)
            p += __shfl_xor_sync(FULL, p, off, 16);
        p += bl;

        if (j == 0) outp[t] = p;

#pragma unroll
        for (int s = 0; s < 15; s++) xs[s] = xs[s + 1];
        xs[15] = p;
    }
}

extern "C" void kernel_launch(void* const* d_in, const int* in_sizes, int n_in,
                              void* d_out, int out_size) {
    const float* y     = (const float*)d_in[0];
    const float* u     = (const float*)d_in[1];
    const float* W_ih  = (const float*)d_in[2];
    const float* W_hh  = (const float*)d_in[3];
    const float* b_ih  = (const float*)d_in[4];
    const float* b_hh  = (const float*)d_in[5];
    const float* W_lin = (const float*)d_in[6];
    const float* b_lin = (const float*)d_in[7];
    const float* W_h0  = (const float*)d_in[8];
    const float* b_h0  = (const float*)d_in[9];
    const float* W_c0  = (const float*)d_in[10];
    const float* b_c0  = (const float*)d_in[11];
    float* out = (float*)d_out;

    lstm_decoder_kernel<<<128, 128>>>(y, u, W_ih, W_hh, b_ih, b_hh,
                                      W_lin, b_lin, W_h0, b_h0, W_c0, b_c0, out);
}

// round 9
// speedup vs baseline: 1.0366x; 1.0366x over previous
#include <cuda_runtime.h>
#include <cstdint>

// LSTMDecoder: B=1024, A=H=16, R=128, T=128.
// 16 threads per batch element; lane j owns h_j, c_j, gate rows of W_hh.
// R8: sync-free shared-memory h broadcast. Convergent warp; STS and LDS are
// warp-wide, processed in order by the per-warp MIO queue -> no __syncwarp.
// asm volatile + memory clobbers pin compiler ordering. h pairs loaded as
// ld.shared.v2.u64 straight into fma.rn.f32x2 operands (no repacking).
// Sigmoid 0.5-scale folded into i/f/o weights+biases.

#define NT 128

__device__ __forceinline__ float tanhapx(float x) {
    float r;
    asm("tanh.approx.f32 %0, %1;" : "=f"(r) : "f"(x));
    return r;
}
__device__ __forceinline__ uint64_t pack2(float lo, float hi) {
    uint64_t r;
    asm("mov.b64 %0, {%1, %2};" : "=l"(r) : "f"(lo), "f"(hi));
    return r;
}
__device__ __forceinline__ void unpack2(float& lo, float& hi, uint64_t v) {
    asm("mov.b64 {%0, %1}, %2;" : "=f"(lo), "=f"(hi) : "l"(v));
}
__device__ __forceinline__ uint64_t fma2v(uint64_t a, uint64_t b, uint64_t c) {
    uint64_t d;
    asm("fma.rn.f32x2 %0, %1, %2, %3;" : "=l"(d) : "l"(a), "l"(b), "l"(c));
    return d;
}
__device__ __forceinline__ uint64_t add2(uint64_t a, uint64_t b) {
    uint64_t r;
    asm("add.rn.f32x2 %0, %1, %2;" : "=l"(r) : "l"(a), "l"(b));
    return r;
}

__global__ __launch_bounds__(128, 1)
void lstm_decoder_kernel(
    const float* __restrict__ y,     // (B,16)
    const float* __restrict__ u,     // (B,128)
    const float* __restrict__ W_ih,  // (64,1)
    const float* __restrict__ W_hh,  // (64,16)
    const float* __restrict__ b_ih,  // (64)
    const float* __restrict__ b_hh,  // (64)
    const float* __restrict__ W_lin, // (1,16)
    const float* __restrict__ b_lin, // (1)
    const float* __restrict__ W_h0,  // (16,128)
    const float* __restrict__ b_h0,  // (16)
    const float* __restrict__ W_c0,  // (16,128)
    const float* __restrict__ b_c0,  // (16)
    float* __restrict__ out)         // (B,144)
{
    const int tid = blockIdx.x * blockDim.x + threadIdx.x;
    const int b   = tid >> 4;     // batch element
    const int j   = tid & 15;     // hidden index
    const unsigned FULL = 0xffffffffu;

    // shared h buffer: 8 batch slots x 16 floats, 16B-aligned for v2.u64 loads
    __shared__ __align__(16) float sh[8 * 16];
    uint32_t sbase;
    asm("{ .reg .u64 t; cvta.to.shared.u64 t, %1; cvt.u32.u64 %0, t; }"
        : "=r"(sbase) : "l"(sh));
    const int bb = threadIdx.x >> 4;              // batch slot in block
    const uint32_t rdaddr = sbase + bb * 64;      // slot base (16 floats)
    const uint32_t wraddr = rdaddr + j * 4;       // this lane's h slot

    // ---- per-thread gate-major packed weight pairs over k ----
    // i,f,o rows pre-scaled by 0.5 (sigmoid folding); g unscaled.
    uint64_t Wi[8], Wf[8], Wg[8], Wo[8];
#pragma unroll
    for (int p = 0; p < 8; p++) {
        Wi[p] = pack2(0.5f * W_hh[(     j) * 16 + 2*p], 0.5f * W_hh[(     j) * 16 + 2*p+1]);
        Wf[p] = pack2(0.5f * W_hh[(16 + j) * 16 + 2*p], 0.5f * W_hh[(16 + j) * 16 + 2*p+1]);
        Wg[p] = pack2(       W_hh[(32 + j) * 16 + 2*p],        W_hh[(32 + j) * 16 + 2*p+1]);
        Wo[p] = pack2(0.5f * W_hh[(48 + j) * 16 + 2*p], 0.5f * W_hh[(48 + j) * 16 + 2*p+1]);
    }
    const uint64_t wxi = pack2(0.5f * W_ih[j],      0.0f);
    const uint64_t wxf = pack2(0.5f * W_ih[16 + j], 0.0f);
    const uint64_t wxg = pack2(       W_ih[32 + j], 0.0f);
    const uint64_t wxo = pack2(0.5f * W_ih[48 + j], 0.0f);
    const uint64_t bvi = pack2(0.5f * (b_ih[j]      + b_hh[j]),      0.0f);
    const uint64_t bvf = pack2(0.5f * (b_ih[16 + j] + b_hh[16 + j]), 0.0f);
    const uint64_t bvg = pack2(       (b_ih[32 + j] + b_hh[32 + j]), 0.0f);
    const uint64_t bvo = pack2(0.5f * (b_ih[48 + j] + b_hh[48 + j]), 0.0f);
    const float wl = W_lin[j];
    const float bl = b_lin[0];

    // ---- h0 = u @ W_h0.T + b_h0 ; c0 = u @ W_c0.T + b_c0 ----
    float h = b_h0[j];
    float c = b_c0[j];
    {
        const float4* u4  = (const float4*)(u    + b * 128);
        const float4* wh4 = (const float4*)(W_h0 + j * 128);
        const float4* wc4 = (const float4*)(W_c0 + j * 128);
#pragma unroll 4
        for (int r = 0; r < 32; r++) {
            float4 uu = u4[r], wh = wh4[r], wc = wc4[r];
            h = fmaf(uu.x, wh.x, h); h = fmaf(uu.y, wh.y, h);
            h = fmaf(uu.z, wh.z, h); h = fmaf(uu.w, wh.w, h);
            c = fmaf(uu.x, wc.x, c); c = fmaf(uu.y, wc.y, c);
            c = fmaf(uu.z, wc.z, c); c = fmaf(uu.w, wc.w, c);
        }
    }

    // ---- window replicated per-thread: xs[s] = window[:, s] ----
    float xs[16];
    {
        const float4* y4 = (const float4*)(y + b * 16);
        float4 y0 = y4[0], y1 = y4[1], y2 = y4[2], y3 = y4[3];
        xs[0]=y0.x; xs[1]=y0.y; xs[2]=y0.z; xs[3]=y0.w;
        xs[4]=y1.x; xs[5]=y1.y; xs[6]=y1.z; xs[7]=y1.w;
        xs[8]=y2.x; xs[9]=y2.y; xs[10]=y2.z; xs[11]=y2.w;
        xs[12]=y3.x; xs[13]=y3.y; xs[14]=y3.z; xs[15]=y3.w;
    }
    out[b * 144 + j] = y[b * 16 + j];        // first 16 output cols = y
    float* outp = out + b * 144 + 16;

    for (int t = 0; t < NT; t++) {
#pragma unroll
        for (int s = 0; s < 16; s++) {
            // publish h (warp-wide STS; in-order MIO makes it visible to the
            // LDS below without a syncwarp in convergent code)
            asm volatile("st.shared.f32 [%0], %1;" :: "r"(wraddr), "f"(h) : "memory");

            // independent work between STS and LDS: x-term chain heads
            uint64_t xd  = pack2(xs[s], xs[s]);
            uint64_t ai0 = fma2v(xd, wxi, bvi);
            uint64_t af0 = fma2v(xd, wxf, bvf);
            uint64_t ag0 = fma2v(xd, wxg, bvg);
            uint64_t ao0 = fma2v(xd, wxo, bvo);

            // h pairs loaded directly as 64-bit f32x2 operands
            uint64_t hp0, hp1, hp2, hp3, hp4, hp5, hp6, hp7;
            asm volatile("ld.shared.v2.u64 {%0, %1}, [%2];"
                         : "=l"(hp0), "=l"(hp1) : "r"(rdaddr)      : "memory");
            asm volatile("ld.shared.v2.u64 {%0, %1}, [%2];"
                         : "=l"(hp2), "=l"(hp3) : "r"(rdaddr + 16) : "memory");
            asm volatile("ld.shared.v2.u64 {%0, %1}, [%2];"
                         : "=l"(hp4), "=l"(hp5) : "r"(rdaddr + 32) : "memory");
            asm volatile("ld.shared.v2.u64 {%0, %1}, [%2];"
                         : "=l"(hp6), "=l"(hp7) : "r"(rdaddr + 48) : "memory");

            // even/odd split FFMA2 chains per gate (depth 5 / 4)
            uint64_t ai1, af1, ag1, ao1;
            ai0 = fma2v(hp0, Wi[0], ai0);  ai1 = fma2v(hp1, Wi[1], 0ull);
            ag0 = fma2v(hp0, Wg[0], ag0);  ag1 = fma2v(hp1, Wg[1], 0ull);
            af0 = fma2v(hp0, Wf[0], af0);  af1 = fma2v(hp1, Wf[1], 0ull);
            ao0 = fma2v(hp0, Wo[0], ao0);  ao1 = fma2v(hp1, Wo[1], 0ull);
            ai0 = fma2v(hp2, Wi[2], ai0);  ai1 = fma2v(hp3, Wi[3], ai1);
            ag0 = fma2v(hp2, Wg[2], ag0);  ag1 = fma2v(hp3, Wg[3], ag1);
            af0 = fma2v(hp2, Wf[2], af0);  af1 = fma2v(hp3, Wf[3], af1);
            ao0 = fma2v(hp2, Wo[2], ao0);  ao1 = fma2v(hp3, Wo[3], ao1);
            ai0 = fma2v(hp4, Wi[4], ai0);  ai1 = fma2v(hp5, Wi[5], ai1);
            ag0 = fma2v(hp4, Wg[4], ag0);  ag1 = fma2v(hp5, Wg[5], ag1);
            af0 = fma2v(hp4, Wf[4], af0);  af1 = fma2v(hp5, Wf[5], af1);
            ao0 = fma2v(hp4, Wo[4], ao0);  ao1 = fma2v(hp5, Wo[5], ao1);
            ai0 = fma2v(hp6, Wi[6], ai0);  ai1 = fma2v(hp7, Wi[7], ai1);
            ag0 = fma2v(hp6, Wg[6], ag0);  ag1 = fma2v(hp7, Wg[7], ag1);
            af0 = fma2v(hp6, Wf[6], af0);  af1 = fma2v(hp7, Wf[7], af1);
            ao0 = fma2v(hp6, Wo[6], ao0);  ao1 = fma2v(hp7, Wo[7], ao1);

            float lo, hi;
            // g and i first: their MUFUs overlap f's, product ready for c-fma
            unpack2(lo, hi, add2(ag0, ag1)); float gg = tanhapx(lo + hi);
            unpack2(lo, hi, add2(ai0, ai1)); float ig = fmaf(0.5f, tanhapx(lo + hi), 0.5f);
            unpack2(lo, hi, add2(af0, af1)); float fg = fmaf(0.5f, tanhapx(lo + hi), 0.5f);
            unpack2(lo, hi, add2(ao0, ao1)); float og = fmaf(0.5f, tanhapx(lo + hi), 0.5f);
            c = fmaf(fg, c, ig * gg);
            h = og * tanhapx(c);
        }
        // pred = sum_j h_j * W_lin_j + b_lin (feeds xs[15], consumed 15 cells
        // later -> off the critical path)
        float p = h * wl;
#pragma unroll
        for (int off = 8; off; off >>= 1)
            p += __shfl_xor_sync(FULL, p, off, 16);
        p += bl;

        if (j == 0) outp[t] = p;

#pragma unroll
        for (int s = 0; s < 15; s++) xs[s] = xs[s + 1];
        xs[15] = p;
    }
}

extern "C" void kernel_launch(void* const* d_in, const int* in_sizes, int n_in,
                              void* d_out, int out_size) {
    const float* y     = (const float*)d_in[0];
    const float* u     = (const float*)d_in[1];
    const float* W_ih  = (const float*)d_in[2];
    const float* W_hh  = (const float*)d_in[3];
    const float* b_ih  = (const float*)d_in[4];
    const float* b_hh  = (const float*)d_in[5];
    const float* W_lin = (const float*)d_in[6];
    const float* b_lin = (const float*)d_in[7];
    const float* W_h0  = (const float*)d_in[8];
    const float* b_h0  = (const float*)d_in[9];
    const float* W_c0  = (const float*)d_in[10];
    const float* b_c0  = (const float*)d_in[11];
    float* out = (float*)d_out;

    lstm_decoder_kernel<<<128, 128>>>(y, u, W_ih, W_hh, b_ih, b_hh,
                                      W_lin, b_lin, W_h0, b_h0, W_c0, b_c0, out);
}